// round 1
// baseline (speedup 1.0000x reference)
#include <cuda_runtime.h>
#include <cuda_bf16.h>

#define NB 8
#define NT 256   // T_en == T_de
#define ND 256
#define NU 256

// Scratch (device globals: no allocation allowed in kernel_launch)
__device__ float d_aeT[NB * NU * NT];  // aeT[b][u][e]  (transposed for coalesced e-reads)
__device__ float d_ad [NB * NT * NU];  // ad [b][t][u]

// ---------------------------------------------------------------------------
// Fused GEMM: computes both att_en (transposed store) and att_de.
//   which=0: C[e][u] = sum_d en[b][e][d] * w_en[d][u]  -> store d_aeT[b][u][e]
//   which=1: C[t][u] = sum_d de[b][t][d] * w_de[d][u]  -> store d_ad [b][t][u]
// 64x64 tile, 256 threads, 4x4 per-thread micro-tile, K-step 16.
// ---------------------------------------------------------------------------
__global__ __launch_bounds__(256) void gemm_kernel(const float* __restrict__ en,
                                                   const float* __restrict__ de,
                                                   const float* __restrict__ w_en,
                                                   const float* __restrict__ w_de)
{
    const int z     = blockIdx.z;
    const int b     = z >> 1;
    const int which = z & 1;

    const float* A  = which ? (de + b * NT * ND) : (en + b * NT * ND);  // (M=256, K=256) row-major
    const float* Bm = which ? w_de : w_en;                               // (K=256, N=256) row-major

    const int m0 = blockIdx.y * 64;
    const int n0 = blockIdx.x * 64;

    __shared__ float As[16][68];  // As[k][m], padded (272B rows keep 16B alignment)
    __shared__ float Bs[16][64];  // Bs[k][n]

    const int tid   = threadIdx.x;
    const int a_row = tid >> 2;          // 0..63
    const int a_k4  = (tid & 3) << 2;    // 0,4,8,12
    const int b_k   = tid >> 4;          // 0..15
    const int b_n4  = (tid & 15) << 2;   // 0..60
    const int tm    = tid >> 4;          // 0..15
    const int tn    = tid & 15;          // 0..15

    float acc[4][4];
#pragma unroll
    for (int i = 0; i < 4; i++)
#pragma unroll
        for (int j = 0; j < 4; j++) acc[i][j] = 0.f;

    for (int k0 = 0; k0 < 256; k0 += 16) {
        float4 av = *(const float4*)(A  + (m0 + a_row) * 256 + k0 + a_k4);
        float4 bv = *(const float4*)(Bm + (k0 + b_k)   * 256 + n0 + b_n4);
        __syncthreads();
        As[a_k4 + 0][a_row] = av.x;
        As[a_k4 + 1][a_row] = av.y;
        As[a_k4 + 2][a_row] = av.z;
        As[a_k4 + 3][a_row] = av.w;
        *(float4*)&Bs[b_k][b_n4] = bv;
        __syncthreads();
#pragma unroll
        for (int k = 0; k < 16; k++) {
            float4 a4 = *(const float4*)&As[k][tm << 2];
            float4 b4 = *(const float4*)&Bs[k][tn << 2];
            float ar[4] = {a4.x, a4.y, a4.z, a4.w};
            float br[4] = {b4.x, b4.y, b4.z, b4.w};
#pragma unroll
            for (int i = 0; i < 4; i++)
#pragma unroll
                for (int j = 0; j < 4; j++)
                    acc[i][j] = fmaf(ar[i], br[j], acc[i][j]);
        }
    }

    if (which == 0) {
        // C[e][u] -> aeT[b][u][e]; per j a float4 along e (contiguous, coalesced)
        float* dst = d_aeT + b * NU * NT;
#pragma unroll
        for (int j = 0; j < 4; j++) {
            int u = n0 + (tn << 2) + j;
            float4 v = make_float4(acc[0][j], acc[1][j], acc[2][j], acc[3][j]);
            *(float4*)(dst + u * NT + m0 + (tm << 2)) = v;
        }
    } else {
        float* dst = d_ad + b * NT * NU;
#pragma unroll
        for (int i = 0; i < 4; i++) {
            int t = m0 + (tm << 2) + i;
            float4 v = make_float4(acc[i][0], acc[i][1], acc[i][2], acc[i][3]);
            *(float4*)(dst + t * NU + n0 + (tn << 2)) = v;
        }
    }
}

// ---------------------------------------------------------------------------
// Fused tanh-score + softmax + context kernel.
// One CTA handles (b, 4 consecutive decoder steps). Thread tid = encoder step e
// for the score phase, = feature d for the context phase.
// mu[t,e] = sum_u nu[u] * tanh(aeT[b][u][e] + ad[b][t][u])
// MUFU tanh.approx is the throughput limiter; ae/en loads amortized 4x.
// ---------------------------------------------------------------------------
__global__ __launch_bounds__(256) void attn_kernel(const float* __restrict__ en,
                                                   const float* __restrict__ de,
                                                   const float* __restrict__ nu,
                                                   float* __restrict__ out)
{
    const int b   = blockIdx.x >> 6;          // 8 b * 64 groups
    const int t0  = (blockIdx.x & 63) << 2;   // 4 decoder rows per CTA
    const int tid = threadIdx.x;

    __shared__ float4 ad4[256];     // (ad[t0..t0+3][u]) packed per u
    __shared__ float  nus[256];
    __shared__ float4 alpha4[256];  // (alpha[t0..t0+3][e]) packed per e
    __shared__ float  red[8];

    {
        const float* adp = d_ad + (b * NT + t0) * NU + tid;
        ad4[tid] = make_float4(adp[0], adp[NU], adp[2 * NU], adp[3 * NU]);
        nus[tid] = nu[tid];
    }
    __syncthreads();

    // ---- scores: thread = e, loop u ----
    const float* ae = d_aeT + b * NU * NT + tid;
    float m0 = 0.f, m1 = 0.f, m2 = 0.f, m3 = 0.f;
#pragma unroll 4
    for (int u = 0; u < 256; ++u) {
        float  a   = ae[u << 8];      // coalesced across threads, L2-resident
        float4 adv = ad4[u];          // LDS.128 broadcast
        float  w   = nus[u];
        float  th;
        asm("tanh.approx.f32 %0, %1;" : "=f"(th) : "f"(a + adv.x)); m0 = fmaf(w, th, m0);
        asm("tanh.approx.f32 %0, %1;" : "=f"(th) : "f"(a + adv.y)); m1 = fmaf(w, th, m1);
        asm("tanh.approx.f32 %0, %1;" : "=f"(th) : "f"(a + adv.z)); m2 = fmaf(w, th, m2);
        asm("tanh.approx.f32 %0, %1;" : "=f"(th) : "f"(a + adv.w)); m3 = fmaf(w, th, m3);
    }

    // ---- softmax over e for each of the 4 rows ----
    float mu[4] = {m0, m1, m2, m3};
    float al[4];
#pragma unroll
    for (int tt = 0; tt < 4; tt++) {
        float v  = mu[tt];
        float mx = v;
#pragma unroll
        for (int o = 16; o; o >>= 1) mx = fmaxf(mx, __shfl_xor_sync(0xffffffffu, mx, o));
        if ((tid & 31) == 0) red[tid >> 5] = mx;
        __syncthreads();
        mx = fmaxf(fmaxf(fmaxf(red[0], red[1]), fmaxf(red[2], red[3])),
                   fmaxf(fmaxf(red[4], red[5]), fmaxf(red[6], red[7])));
        __syncthreads();
        float ex = __expf(v - mx);
        float s  = ex;
#pragma unroll
        for (int o = 16; o; o >>= 1) s += __shfl_xor_sync(0xffffffffu, s, o);
        if ((tid & 31) == 0) red[tid >> 5] = s;
        __syncthreads();
        s = ((red[0] + red[1]) + (red[2] + red[3])) + ((red[4] + red[5]) + (red[6] + red[7]));
        __syncthreads();
        al[tt] = __fdividef(ex, s);
    }
    alpha4[tid] = make_float4(al[0], al[1], al[2], al[3]);
    __syncthreads();

    // ---- context: thread = d, loop e ----
    const float* enb = en + b * NT * ND + tid;
    const float* dep = de + (b * NT + t0) * ND + tid;
    float o0 = dep[0], o1 = dep[ND], o2 = dep[2 * ND], o3 = dep[3 * ND];
#pragma unroll 4
    for (int e = 0; e < 256; ++e) {
        float  v = enb[e << 8];       // coalesced, amortized over 4 rows
        float4 a = alpha4[e];
        o0 = fmaf(a.x, v, o0);
        o1 = fmaf(a.y, v, o1);
        o2 = fmaf(a.z, v, o2);
        o3 = fmaf(a.w, v, o3);
    }
    float* op = out + (b * NT + t0) * ND + tid;
    op[0] = o0; op[ND] = o1; op[2 * ND] = o2; op[3 * ND] = o3;
}

extern "C" void kernel_launch(void* const* d_in, const int* in_sizes, int n_in,
                              void* d_out, int out_size)
{
    const float* en   = (const float*)d_in[0];   // (8,256,256)
    const float* de   = (const float*)d_in[1];   // (8,256,256)
    const float* w_en = (const float*)d_in[2];   // (256,256)
    const float* w_de = (const float*)d_in[3];   // (256,256)
    const float* nu   = (const float*)d_in[4];   // (256,1)
    float* out = (float*)d_out;                  // (8,256,256) fp32

    dim3 gg(4, 4, 16);                // 4 n-tiles, 4 m-tiles, 8 b * 2 matrices
    gemm_kernel<<<gg, 256>>>(en, de, w_en, w_de);
    attn_kernel<<<NB * (NT / 4), 256>>>(en, de, nu, out);
}